// round 11
// baseline (speedup 1.0000x reference)
#include <cuda_runtime.h>
#include <cuda_bf16.h>
#include <cstdint>
#include <cstddef>

#define BB 32
#define TT 512
#define DD 512
#define UU 512

// ---------------------------------------------------------------------------
// Device-global scratch (no cudaMalloc allowed)
// ---------------------------------------------------------------------------
__device__ float    g_mx[(size_t)BB * TT * 3 * UU];   // x@kernel + bias
__device__ float    g_rh[BB * UU];                    // r*h exchange buffer
__device__ unsigned g_flags[8][32];                   // per-CTA step flags
                                                      // (16 used, 128B/group)

__device__ __forceinline__ float hsig(float x) {
    return fminf(fmaxf(fmaf(0.2f, x, 0.5f), 0.0f), 1.0f);
}
__device__ __forceinline__ unsigned flag_ld(const unsigned* p) {
    unsigned v;
    asm volatile("ld.acquire.gpu.u32 %0, [%1];" : "=r"(v) : "l"(p) : "memory");
    return v;
}
__device__ __forceinline__ void flag_st(unsigned* p, unsigned v) {
    asm volatile("st.release.gpu.u32 [%0], %1;" :: "l"(p), "r"(v) : "memory");
}

// ---------------------------------------------------------------------------
// Kernel 1: mx = x @ kernel + bias   (M=16384, N=1536, K=512)
// ---------------------------------------------------------------------------
__global__ __launch_bounds__(256) void mx_gemm(const float* __restrict__ X,
                                               const float* __restrict__ W,
                                               const float* __restrict__ bias) {
    __shared__ float As[16][132];
    __shared__ float Bs[16][68];

    const int tid = threadIdx.x;
    const int m0  = blockIdx.y * 128;
    const int n0  = blockIdx.x * 64;
    const int tm  = tid & 15;
    const int tn  = tid >> 4;

    float acc[8][4];
#pragma unroll
    for (int i = 0; i < 8; i++)
#pragma unroll
        for (int j = 0; j < 4; j++) acc[i][j] = 0.0f;

    for (int kk = 0; kk < DD; kk += 16) {
#pragma unroll
        for (int jj = 0; jj < 2; jj++) {
            int idx = tid + jj * 256;
            int r   = idx >> 2;
            int kq  = (idx & 3) << 2;
            float4 v = *(const float4*)&X[(size_t)(m0 + r) * DD + kk + kq];
            As[kq + 0][r] = v.x;
            As[kq + 1][r] = v.y;
            As[kq + 2][r] = v.z;
            As[kq + 3][r] = v.w;
        }
        {
            int kr = tid >> 4;
            int nq = (tid & 15) << 2;
            float4 v = *(const float4*)&W[(size_t)(kk + kr) * (3 * UU) + n0 + nq];
            *(float4*)&Bs[kr][nq] = v;
        }
        __syncthreads();

#pragma unroll
        for (int k = 0; k < 16; k++) {
            float4 a0 = *(const float4*)&As[k][tm << 2];
            float4 a1 = *(const float4*)&As[k][64 + (tm << 2)];
            float4 b0 = *(const float4*)&Bs[k][tn << 2];
            float af[8] = {a0.x, a0.y, a0.z, a0.w, a1.x, a1.y, a1.z, a1.w};
            float bf[4] = {b0.x, b0.y, b0.z, b0.w};
#pragma unroll
            for (int i = 0; i < 8; i++)
#pragma unroll
                for (int j = 0; j < 4; j++) acc[i][j] = fmaf(af[i], bf[j], acc[i][j]);
        }
        __syncthreads();
    }

    float4 bv = *(const float4*)&bias[n0 + (tn << 2)];
#pragma unroll
    for (int i = 0; i < 8; i++) {
        int m = (i < 4) ? ((tm << 2) + i) : (64 + (tm << 2) + (i - 4));
        float4 o;
        o.x = acc[i][0] + bv.x;
        o.y = acc[i][1] + bv.y;
        o.z = acc[i][2] + bv.z;
        o.w = acc[i][3] + bv.w;
        *(float4*)&g_mx[(size_t)(m0 + m) * (3 * UU) + n0 + (tn << 2)] = o;
    }
}

#define RED2(v) do { \
    (v) += __shfl_xor_sync(0xffffffffu, (v), 8);  \
    (v) += __shfl_xor_sync(0xffffffffu, (v), 16); \
} while (0)

// ===========================================================================
// GRU recurrence: 128 CTAs = 8 groups (x4 batches) * 16 col-CTAs (x32 cols),
// 512 threads, 1 CTA/SM. Per-CTA release flags; warp k waits only on peer k
// and immediately stages its slice (pipelined detect+load). z-GEMM in the
// rh window; z and h_own carried in registers. Wz+Wr in regs, Wh in SMEM.
// ===========================================================================
struct SMX {
    float wh[512 * 32];     // 64 KB
    float stage[4][512];    // 8 KB (h, then rh)
    float red[16 * 128];    // 8 KB
};
#define SMX_BYTES ((int)sizeof(SMX))

__global__ __launch_bounds__(512, 1) void gru16(const float* __restrict__ RK,
                                                float* __restrict__ out) {
    extern __shared__ char raw[];
    SMX* s = (SMX*)raw;
    __shared__ unsigned s_base;

    const int tid = threadIdx.x;
    const int grp = blockIdx.x >> 4;          // 0..7
    const int cid = blockIdx.x & 15;          // 0..15
    const int gb0 = grp << 2;
    const int j0  = cid << 5;                 // 32 unit cols

    const int ks = tid >> 3;                  // 0..63, u = ks*8 .. +7
    const int cs = tid & 7;                   // cols cs*4 .. +3
    const int ub = ks << 3;
    const int w  = tid >> 5;                  // warp 0..15 == peer id
    const int l  = tid & 31;

    const int gate = tid >> 7;                // tid<256: 0=z, 1=r
    const int rb   = (tid >> 5) & 3;
    const int rc   = tid & 31;

    // staging lane map: warp w stages peer w's 4x32 slice
    const int sb = l >> 3;                    // batch 0..3
    const int sc = (l & 7) << 2;              // col quad within peer's 32

    // ---- weights: Wh -> SMEM, Wz/Wr -> registers ----
    for (int i = tid; i < (512 * 32) / 4; i += 512) {
        int f = i << 2;
        int u = f >> 5, c = f & 31;
        *(float4*)&s->wh[f] = *(const float4*)&RK[(size_t)u * 1536 + 1024 + j0 + c];
    }
    float4 wz[8], wr[8];
#pragma unroll
    for (int uu = 0; uu < 8; uu++) {
        const float* bp = &RK[(size_t)(ub + uu) * 1536 + j0 + (cs << 2)];
        wz[uu] = *(const float4*)bp;
        wr[uu] = *(const float4*)(bp + 512);
    }

    if (tid == 0) s_base = flag_ld(&g_flags[grp][cid]);
    __syncthreads();
    const unsigned base = s_base;

    float hp = 0.0f;   // own h value, carried in register (threads 0..127)

    // ---- t = 0 : h_prev = 0 ----
    if (tid < 128) {
        size_t mrow = (size_t)(gb0 + rb) * TT * 1536;
        float z  = hsig(g_mx[mrow + j0 + rc]);
        float hh = tanhf(g_mx[mrow + 1024 + j0 + rc]);
        hp = (1.0f - z) * hh;
        out[(size_t)(gb0 + rb) * TT * UU + j0 + rc] = hp;
    }
    __syncthreads();
    if (tid == 0) flag_st(&g_flags[grp][cid], base + 1u);

#pragma unroll 1
    for (int t = 1; t < TT; t++) {
        // prefetch mx gate terms (independent of sync)
        float pm1 = 0.0f, pm2 = 0.0f;
        if (tid < 256) {
            size_t mrow = ((size_t)(gb0 + rb) * TT + t) * 1536;
            pm1 = __ldcg(&g_mx[mrow + (gate << 9) + j0 + rc]);
            if (tid < 128) pm2 = __ldcg(&g_mx[mrow + 1024 + j0 + rc]);
        }

        // ---- per-peer wait + stage h(t-1): warp w handles peer w ----
        {
            unsigned need = base + (unsigned)(2 * t - 1);
            if (l == 0) {
                const unsigned* fp = &g_flags[grp][w];
                while ((int)(flag_ld(fp) - need) < 0) { }
            }
            __syncwarp();
            float4 v = __ldcg((const float4*)(
                out + ((size_t)(gb0 + sb) * TT + (t - 1)) * UU + (w << 5) + sc));
            *(float4*)&s->stage[sb][(w << 5) + sc] = v;
        }
        __syncthreads();

        // ---- r pass (critical path) ----
        {
            float a[4][4];
#pragma unroll
            for (int b = 0; b < 4; b++)
#pragma unroll
                for (int c = 0; c < 4; c++) a[b][c] = 0.0f;
#pragma unroll
            for (int uu = 0; uu < 8; uu++) {
                int u = ub + uu;
                float4 wv = wr[uu];
                float h0 = s->stage[0][u], h1 = s->stage[1][u];
                float h2 = s->stage[2][u], h3 = s->stage[3][u];
                a[0][0] = fmaf(h0, wv.x, a[0][0]); a[0][1] = fmaf(h0, wv.y, a[0][1]);
                a[0][2] = fmaf(h0, wv.z, a[0][2]); a[0][3] = fmaf(h0, wv.w, a[0][3]);
                a[1][0] = fmaf(h1, wv.x, a[1][0]); a[1][1] = fmaf(h1, wv.y, a[1][1]);
                a[1][2] = fmaf(h1, wv.z, a[1][2]); a[1][3] = fmaf(h1, wv.w, a[1][3]);
                a[2][0] = fmaf(h2, wv.x, a[2][0]); a[2][1] = fmaf(h2, wv.y, a[2][1]);
                a[2][2] = fmaf(h2, wv.z, a[2][2]); a[2][3] = fmaf(h2, wv.w, a[2][3]);
                a[3][0] = fmaf(h3, wv.x, a[3][0]); a[3][1] = fmaf(h3, wv.y, a[3][1]);
                a[3][2] = fmaf(h3, wv.z, a[3][2]); a[3][3] = fmaf(h3, wv.w, a[3][3]);
            }
#pragma unroll
            for (int b = 0; b < 4; b++)
#pragma unroll
                for (int c = 0; c < 4; c++) RED2(a[b][c]);
            if (l < 8)
#pragma unroll
                for (int b = 0; b < 4; b++)
                    *(float4*)&s->red[(w << 7) + (b << 5) + (l << 2)] =
                        make_float4(a[b][0], a[b][1], a[b][2], a[b][3]);
        }
        __syncthreads();

        // ---- r reduce -> publish rh (threads 128..255 hold pm1 = mx_r) ----
        if (gate == 1) {
            int idx = tid - 128;
            float sum = pm1;
#pragma unroll
            for (int k = 0; k < 16; k++) sum += s->red[(k << 7) + idx];
            float r = hsig(sum);
            g_rh[(size_t)(gb0 + rb) * UU + j0 + rc] = r * s->stage[rb][j0 + rc];
        }
        __syncthreads();
        if (tid == 0) flag_st(&g_flags[grp][cid], base + (unsigned)(2 * t));

        // ======== hidden work: z pass while peers publish rh ========
        {
            float a[4][4];
#pragma unroll
            for (int b = 0; b < 4; b++)
#pragma unroll
                for (int c = 0; c < 4; c++) a[b][c] = 0.0f;
#pragma unroll
            for (int uu = 0; uu < 8; uu++) {
                int u = ub + uu;
                float4 wv = wz[uu];
                float h0 = s->stage[0][u], h1 = s->stage[1][u];
                float h2 = s->stage[2][u], h3 = s->stage[3][u];
                a[0][0] = fmaf(h0, wv.x, a[0][0]); a[0][1] = fmaf(h0, wv.y, a[0][1]);
                a[0][2] = fmaf(h0, wv.z, a[0][2]); a[0][3] = fmaf(h0, wv.w, a[0][3]);
                a[1][0] = fmaf(h1, wv.x, a[1][0]); a[1][1] = fmaf(h1, wv.y, a[1][1]);
                a[1][2] = fmaf(h1, wv.z, a[1][2]); a[1][3] = fmaf(h1, wv.w, a[1][3]);
                a[2][0] = fmaf(h2, wv.x, a[2][0]); a[2][1] = fmaf(h2, wv.y, a[2][1]);
                a[2][2] = fmaf(h2, wv.z, a[2][2]); a[2][3] = fmaf(h2, wv.w, a[2][3]);
                a[3][0] = fmaf(h3, wv.x, a[3][0]); a[3][1] = fmaf(h3, wv.y, a[3][1]);
                a[3][2] = fmaf(h3, wv.z, a[3][2]); a[3][3] = fmaf(h3, wv.w, a[3][3]);
            }
#pragma unroll
            for (int b = 0; b < 4; b++)
#pragma unroll
                for (int c = 0; c < 4; c++) RED2(a[b][c]);
            if (l < 8)
#pragma unroll
                for (int b = 0; b < 4; b++)
                    *(float4*)&s->red[(w << 7) + (b << 5) + (l << 2)] =
                        make_float4(a[b][0], a[b][1], a[b][2], a[b][3]);
        }
        __syncthreads();
        // ============================================================

        // ---- per-peer wait + stage rh; z-reduce hidden under loads ----
        float zreg = 0.0f;
        {
            unsigned need = base + (unsigned)(2 * t);
            if (l == 0) {
                const unsigned* fp = &g_flags[grp][w];
                while ((int)(flag_ld(fp) - need) < 0) { }
            }
            __syncwarp();
            float4 v = __ldcg((const float4*)(
                g_rh + (size_t)(gb0 + sb) * UU + (w << 5) + sc));
            if (tid < 128) {          // z-reduce (red holds z partials)
                float sum = pm1;
#pragma unroll
                for (int k = 0; k < 16; k++) sum += s->red[(k << 7) + tid];
                zreg = hsig(sum);
            }
            *(float4*)&s->stage[sb][(w << 5) + sc] = v;
        }
        __syncthreads();

        // ---- h-candidate pass (Wh from SMEM) ----
        {
            float a[4][4];
#pragma unroll
            for (int b = 0; b < 4; b++)
#pragma unroll
                for (int c = 0; c < 4; c++) a[b][c] = 0.0f;
#pragma unroll
            for (int uu = 0; uu < 8; uu++) {
                int u = ub + uu;
                float4 wv = *(const float4*)&s->wh[(u << 5) + (cs << 2)];
                float h0 = s->stage[0][u], h1 = s->stage[1][u];
                float h2 = s->stage[2][u], h3 = s->stage[3][u];
                a[0][0] = fmaf(h0, wv.x, a[0][0]); a[0][1] = fmaf(h0, wv.y, a[0][1]);
                a[0][2] = fmaf(h0, wv.z, a[0][2]); a[0][3] = fmaf(h0, wv.w, a[0][3]);
                a[1][0] = fmaf(h1, wv.x, a[1][0]); a[1][1] = fmaf(h1, wv.y, a[1][1]);
                a[1][2] = fmaf(h1, wv.z, a[1][2]); a[1][3] = fmaf(h1, wv.w, a[1][3]);
                a[2][0] = fmaf(h2, wv.x, a[2][0]); a[2][1] = fmaf(h2, wv.y, a[2][1]);
                a[2][2] = fmaf(h2, wv.z, a[2][2]); a[2][3] = fmaf(h2, wv.w, a[2][3]);
                a[3][0] = fmaf(h3, wv.x, a[3][0]); a[3][1] = fmaf(h3, wv.y, a[3][1]);
                a[3][2] = fmaf(h3, wv.z, a[3][2]); a[3][3] = fmaf(h3, wv.w, a[3][3]);
            }
#pragma unroll
            for (int b = 0; b < 4; b++)
#pragma unroll
                for (int c = 0; c < 4; c++) RED2(a[b][c]);
            if (l < 8)
#pragma unroll
                for (int b = 0; b < 4; b++)
                    *(float4*)&s->red[(w << 7) + (b << 5) + (l << 2)] =
                        make_float4(a[b][0], a[b][1], a[b][2], a[b][3]);
        }
        __syncthreads();

        // ---- final: h(t) ----
        if (tid < 128) {
            float sum = pm2;
#pragma unroll
            for (int k = 0; k < 16; k++) sum += s->red[(k << 7) + tid];
            float hh = tanhf(sum);
            float hn = zreg * hp + (1.0f - zreg) * hh;
            out[((size_t)(gb0 + rb) * TT + t) * UU + j0 + rc] = hn;
            hp = hn;
        }
        __syncthreads();
        if (tid == 0) flag_st(&g_flags[grp][cid], base + (unsigned)(2 * t + 1));
    }
}

// ---------------------------------------------------------------------------
extern "C" void kernel_launch(void* const* d_in, const int* in_sizes, int n_in,
                              void* d_out, int out_size) {
    const float* x    = (const float*)d_in[0];
    const float* ker  = (const float*)d_in[1];
    const float* rk   = (const float*)d_in[2];
    const float* bias = (const float*)d_in[3];
    float* out = (float*)d_out;
    (void)in_sizes; (void)n_in; (void)out_size;

    static bool attr_set = false;
    if (!attr_set) {
        cudaFuncSetAttribute(gru16, cudaFuncAttributeMaxDynamicSharedMemorySize,
                             SMX_BYTES);
        attr_set = true;
    }

    dim3 gg(24, 128);
    mx_gemm<<<gg, 256>>>(x, ker, bias);
    gru16<<<128, 512, SMX_BYTES>>>(rk, out);
}

// round 12
// speedup vs baseline: 1.0233x; 1.0233x over previous
#include <cuda_runtime.h>
#include <cuda_bf16.h>
#include <cstdint>
#include <cstddef>

#define BB 32
#define TT 512
#define DD 512
#define UU 512

// ---------------------------------------------------------------------------
// Device-global scratch (no cudaMalloc allowed)
// ---------------------------------------------------------------------------
__device__ float    g_mx[(size_t)BB * TT * 3 * UU];   // x@kernel + bias
__device__ float    g_rh[BB * UU];                    // r*h exchange buffer
__device__ unsigned g_cnt[8];                         // cumulative arrivals
__device__ unsigned g_ep[8];                          // published epoch
__device__ unsigned g_prog[4];                        // mx chunk progress

__device__ __forceinline__ float hsig(float x) {
    return fminf(fmaxf(fmaf(0.2f, x, 0.5f), 0.0f), 1.0f);
}

__global__ void init_prog() {
    if (threadIdx.x < 4) g_prog[threadIdx.x] = 0u;
}

// ---------------------------------------------------------------------------
// mx tile producer: one 128x128 tile of mx = x@kernel + bias, 512 threads.
// tile g in [0,1536): chunk = g/384 (t-range), inner: b = (g%384)/12, nt = g%12
// ---------------------------------------------------------------------------
__device__ void mx_tile(const float* __restrict__ X, const float* __restrict__ W,
                        const float* __restrict__ bias, char* smraw, int g) {
    float (*As)[132] = (float(*)[132])smraw;
    float (*Bs)[132] = (float(*)[132])(smraw + 16 * 132 * 4);

    const int tid  = threadIdx.x;
    const int chunk = g / 384;
    const int inner = g % 384;
    const int b  = inner / 12;
    const int nt = inner % 12;
    const int m0 = b * 512 + chunk * 128;
    const int n0 = nt * 128;
    const int tm = tid & 15;
    const int tn = tid >> 4;          // 0..31

    float acc[8][4];
#pragma unroll
    for (int i = 0; i < 8; i++)
#pragma unroll
        for (int j = 0; j < 4; j++) acc[i][j] = 0.0f;

    for (int kk = 0; kk < DD; kk += 16) {
        {
            int r  = tid >> 2;
            int kq = (tid & 3) << 2;
            float4 v = *(const float4*)&X[(size_t)(m0 + r) * DD + kk + kq];
            As[kq + 0][r] = v.x; As[kq + 1][r] = v.y;
            As[kq + 2][r] = v.z; As[kq + 3][r] = v.w;
        }
        {
            int kr = tid >> 5;
            int nq = (tid & 31) << 2;
            float4 v = *(const float4*)&W[(size_t)(kk + kr) * (3 * UU) + n0 + nq];
            *(float4*)&Bs[kr][nq] = v;
        }
        __syncthreads();
#pragma unroll
        for (int k = 0; k < 16; k++) {
            float4 a0 = *(const float4*)&As[k][tm << 2];
            float4 a1 = *(const float4*)&As[k][64 + (tm << 2)];
            float4 b0 = *(const float4*)&Bs[k][tn << 2];
            float af[8] = {a0.x, a0.y, a0.z, a0.w, a1.x, a1.y, a1.z, a1.w};
            float bf[4] = {b0.x, b0.y, b0.z, b0.w};
#pragma unroll
            for (int i = 0; i < 8; i++)
#pragma unroll
                for (int j = 0; j < 4; j++) acc[i][j] = fmaf(af[i], bf[j], acc[i][j]);
        }
        __syncthreads();
    }

    float4 bv = *(const float4*)&bias[n0 + (tn << 2)];
#pragma unroll
    for (int i = 0; i < 8; i++) {
        int m = (i < 4) ? ((tm << 2) + i) : (64 + (tm << 2) + (i - 4));
        float4 o;
        o.x = acc[i][0] + bv.x; o.y = acc[i][1] + bv.y;
        o.z = acc[i][2] + bv.z; o.w = acc[i][3] + bv.w;
        *(float4*)&g_mx[(size_t)(m0 + m) * (3 * UU) + n0 + (tn << 2)] = o;
    }
    __threadfence();
    __syncthreads();
    if (tid == 0) atomicAdd(&g_prog[chunk], 1u);
}

#define RED2(v) do { \
    (v) += __shfl_xor_sync(0xffffffffu, (v), 8);  \
    (v) += __shfl_xor_sync(0xffffffffu, (v), 16); \
} while (0)

// ===========================================================================
// Fused kernel. CTAs 0..127: GRU scan (R10 layout: 8 groups x 16 col-CTAs,
// 512 thr, Wz/Wr in regs, Wh in SMEM, split atomic barrier, z in rh window).
// CTAs 128..: mx producers for chunks 1..3. All CTAs co-produce chunk 0 first.
// ===========================================================================
struct SMX {
    float wh[512 * 32];     // 64 KB
    float stage[4][512];    // 8 KB
    float red[16 * 128];    // 8 KB
    float zs[128], hown[128];
    unsigned ep0;
};
#define SMX_BYTES ((int)sizeof(SMX))

__global__ __launch_bounds__(512, 1) void gru_fused(
    const float* __restrict__ X, const float* __restrict__ W,
    const float* __restrict__ RK, const float* __restrict__ bias,
    float* __restrict__ out) {
    extern __shared__ char raw[];
    SMX* s = (SMX*)raw;
    const int tid = threadIdx.x;
    const int bid = blockIdx.x;
    const int nmx = (int)gridDim.x - 128;

    // ---- phase A: all CTAs cooperatively produce mx chunk 0 ----
    for (int g = bid; g < 384; g += (int)gridDim.x)
        mx_tile(X, W, bias, raw, g);

    // ---- producer CTAs: chunks 1..3, then exit ----
    if (bid >= 128) {
        for (int g = 384 + (bid - 128); g < 1536; g += nmx)
            mx_tile(X, W, bias, raw, g);
        return;
    }

    // ---- GRU role ----
    const int grp = bid >> 4;                 // 0..7
    const int gb0 = grp << 2;
    const int j0  = (bid & 15) << 5;          // 32 unit cols

    const int ks = tid >> 3;                  // 0..63
    const int cs = tid & 7;
    const int ub = ks << 3;
    const int w  = tid >> 5;
    const int l  = tid & 31;

    const int gate = tid >> 7;                // tid<256: 0=z, 1=r
    const int rb   = (tid >> 5) & 3;
    const int rc   = tid & 31;

    auto CHUNK_WAIT = [&](int c) {
        if (tid == 0) {
            while (*(volatile unsigned*)&g_prog[c] < 384u) __nanosleep(64);
        }
        __syncthreads();
    };

    // weights: Wh -> SMEM, Wz/Wr -> registers
    __syncthreads();   // phase-A smem reuse barrier
    for (int i = tid; i < (512 * 32) / 4; i += 512) {
        int f = i << 2;
        int u = f >> 5, c = f & 31;
        *(float4*)&s->wh[f] = *(const float4*)&RK[(size_t)u * 1536 + 1024 + j0 + c];
    }
    float4 wz[8], wr[8];
#pragma unroll
    for (int uu = 0; uu < 8; uu++) {
        const float* bp = &RK[(size_t)(ub + uu) * 1536 + j0 + (cs << 2)];
        wz[uu] = *(const float4*)bp;
        wr[uu] = *(const float4*)(bp + 512);
    }

    if (tid == 0) s->ep0 = *(volatile unsigned*)&g_ep[grp];
    __syncthreads();
    const unsigned base = s->ep0;
    unsigned tgt = base;

    auto ARRIVE = [&]() {
        __threadfence();
        __syncthreads();
        if (tid == 0) {
            unsigned p = atomicAdd(&g_cnt[grp], 1u);
            if (((p + 1u) & 15u) == 0u) {
                __threadfence();
                *(volatile unsigned*)&g_ep[grp] = (p + 1u) >> 4;
            }
        }
    };
    auto WAIT = [&](unsigned target) {
        if (tid == 0) {
            while ((int)(*(volatile unsigned*)&g_ep[grp] - target) < 0)
                __nanosleep(32);
        }
        __syncthreads();
    };

    // chunk 0 fully ready (other CTAs' phase-A tiles)
    CHUNK_WAIT(0);

    // ---- t = 0 : h_prev = 0 ----
    if (tid < 128) {
        size_t mrow = (size_t)(gb0 + rb) * TT * 1536;
        float z  = hsig(__ldcg(&g_mx[mrow + j0 + rc]));
        float hh = tanhf(__ldcg(&g_mx[mrow + 1024 + j0 + rc]));
        out[(size_t)(gb0 + rb) * TT * UU + j0 + rc] = (1.0f - z) * hh;
    }
    ARRIVE(); ++tgt;

#pragma unroll 1
    for (int t = 1; t < TT; t++) {
        if ((t & 127) == 0) CHUNK_WAIT(t >> 7);

        // prefetch mx gate terms
        float pm1 = 0.0f, pm2 = 0.0f;
        if (tid < 256) {
            size_t mrow = ((size_t)(gb0 + rb) * TT + t) * 1536;
            pm1 = __ldcg(&g_mx[mrow + (gate << 9) + j0 + rc]);
            if (tid < 128) pm2 = __ldcg(&g_mx[mrow + 1024 + j0 + rc]);
        }

        // ---- wait h(t-1) ----
        WAIT(tgt);

        // ---- stage h(t-1) ----
        {
            int b = tid >> 7, ug = tid & 127;
            float4 v = __ldcg(
                (const float4*)(out + ((size_t)(gb0 + b) * TT + (t - 1)) * UU) + ug);
            *(float4*)&s->stage[b][ug << 2] = v;
        }
        __syncthreads();

        // ---- r pass ----
        {
            float a[4][4];
#pragma unroll
            for (int b = 0; b < 4; b++)
#pragma unroll
                for (int c = 0; c < 4; c++) a[b][c] = 0.0f;
#pragma unroll
            for (int uu = 0; uu < 8; uu++) {
                int u = ub + uu;
                float4 wv = wr[uu];
                float h0 = s->stage[0][u], h1 = s->stage[1][u];
                float h2 = s->stage[2][u], h3 = s->stage[3][u];
                a[0][0] = fmaf(h0, wv.x, a[0][0]); a[0][1] = fmaf(h0, wv.y, a[0][1]);
                a[0][2] = fmaf(h0, wv.z, a[0][2]); a[0][3] = fmaf(h0, wv.w, a[0][3]);
                a[1][0] = fmaf(h1, wv.x, a[1][0]); a[1][1] = fmaf(h1, wv.y, a[1][1]);
                a[1][2] = fmaf(h1, wv.z, a[1][2]); a[1][3] = fmaf(h1, wv.w, a[1][3]);
                a[2][0] = fmaf(h2, wv.x, a[2][0]); a[2][1] = fmaf(h2, wv.y, a[2][1]);
                a[2][2] = fmaf(h2, wv.z, a[2][2]); a[2][3] = fmaf(h2, wv.w, a[2][3]);
                a[3][0] = fmaf(h3, wv.x, a[3][0]); a[3][1] = fmaf(h3, wv.y, a[3][1]);
                a[3][2] = fmaf(h3, wv.z, a[3][2]); a[3][3] = fmaf(h3, wv.w, a[3][3]);
            }
#pragma unroll
            for (int b = 0; b < 4; b++)
#pragma unroll
                for (int c = 0; c < 4; c++) RED2(a[b][c]);
            if (l < 8)
#pragma unroll
                for (int b = 0; b < 4; b++)
                    *(float4*)&s->red[(w << 7) + (b << 5) + (l << 2)] =
                        make_float4(a[b][0], a[b][1], a[b][2], a[b][3]);
        }
        __syncthreads();

        // ---- r reduce -> publish rh ----
        if (gate == 1 && tid < 256) {
            int idx = tid - 128;
            float sum = pm1;
#pragma unroll
            for (int k = 0; k < 16; k++) sum += s->red[(k << 7) + idx];
            float r = hsig(sum);
            g_rh[(size_t)(gb0 + rb) * UU + j0 + rc] = r * s->stage[rb][j0 + rc];
        }
        ARRIVE(); ++tgt;

        // ======== hidden: z pass while peers publish rh ========
        {
            float a[4][4];
#pragma unroll
            for (int b = 0; b < 4; b++)
#pragma unroll
                for (int c = 0; c < 4; c++) a[b][c] = 0.0f;
#pragma unroll
            for (int uu = 0; uu < 8; uu++) {
                int u = ub + uu;
                float4 wv = wz[uu];
                float h0 = s->stage[0][u], h1 = s->stage[1][u];
                float h2 = s->stage[2][u], h3 = s->stage[3][u];
                a[0][0] = fmaf(h0, wv.x, a[0][0]); a[0][1] = fmaf(h0, wv.y, a[0][1]);
                a[0][2] = fmaf(h0, wv.z, a[0][2]); a[0][3] = fmaf(h0, wv.w, a[0][3]);
                a[1][0] = fmaf(h1, wv.x, a[1][0]); a[1][1] = fmaf(h1, wv.y, a[1][1]);
                a[1][2] = fmaf(h1, wv.z, a[1][2]); a[1][3] = fmaf(h1, wv.w, a[1][3]);
                a[2][0] = fmaf(h2, wv.x, a[2][0]); a[2][1] = fmaf(h2, wv.y, a[2][1]);
                a[2][2] = fmaf(h2, wv.z, a[2][2]); a[2][3] = fmaf(h2, wv.w, a[2][3]);
                a[3][0] = fmaf(h3, wv.x, a[3][0]); a[3][1] = fmaf(h3, wv.y, a[3][1]);
                a[3][2] = fmaf(h3, wv.z, a[3][2]); a[3][3] = fmaf(h3, wv.w, a[3][3]);
            }
#pragma unroll
            for (int b = 0; b < 4; b++)
#pragma unroll
                for (int c = 0; c < 4; c++) RED2(a[b][c]);
            if (l < 8)
#pragma unroll
                for (int b = 0; b < 4; b++)
                    *(float4*)&s->red[(w << 7) + (b << 5) + (l << 2)] =
                        make_float4(a[b][0], a[b][1], a[b][2], a[b][3]);
        }
        __syncthreads();
        if (gate == 0 && tid < 128) {
            float sum = pm1;
#pragma unroll
            for (int k = 0; k < 16; k++) sum += s->red[(k << 7) + tid];
            s->zs[tid]   = hsig(sum);
            s->hown[tid] = s->stage[rb][j0 + rc];
        }
        // ========================================================

        // ---- wait rh, stage it ----
        WAIT(tgt);
        {
            int b = tid >> 7, ug = tid & 127;
            float4 v = __ldcg((const float4*)(g_rh + (size_t)(gb0 + b) * UU) + ug);
            *(float4*)&s->stage[b][ug << 2] = v;
        }
        __syncthreads();

        // ---- h-candidate pass ----
        {
            float a[4][4];
#pragma unroll
            for (int b = 0; b < 4; b++)
#pragma unroll
                for (int c = 0; c < 4; c++) a[b][c] = 0.0f;
#pragma unroll
            for (int uu = 0; uu < 8; uu++) {
                int u = ub + uu;
                float4 wv = *(const float4*)&s->wh[(u << 5) + (cs << 2)];
                float h0 = s->stage[0][u], h1 = s->stage[1][u];
                float h2 = s->stage[2][u], h3 = s->stage[3][u];
                a[0][0] = fmaf(h0, wv.x, a[0][0]); a[0][1] = fmaf(h0, wv.y, a[0][1]);
                a[0][2] = fmaf(h0, wv.z, a[0][2]); a[0][3] = fmaf(h0, wv.w, a[0][3]);
                a[1][0] = fmaf(h1, wv.x, a[1][0]); a[1][1] = fmaf(h1, wv.y, a[1][1]);
                a[1][2] = fmaf(h1, wv.z, a[1][2]); a[1][3] = fmaf(h1, wv.w, a[1][3]);
                a[2][0] = fmaf(h2, wv.x, a[2][0]); a[2][1] = fmaf(h2, wv.y, a[2][1]);
                a[2][2] = fmaf(h2, wv.z, a[2][2]); a[2][3] = fmaf(h2, wv.w, a[2][3]);
                a[3][0] = fmaf(h3, wv.x, a[3][0]); a[3][1] = fmaf(h3, wv.y, a[3][1]);
                a[3][2] = fmaf(h3, wv.z, a[3][2]); a[3][3] = fmaf(h3, wv.w, a[3][3]);
            }
#pragma unroll
            for (int b = 0; b < 4; b++)
#pragma unroll
                for (int c = 0; c < 4; c++) RED2(a[b][c]);
            if (l < 8)
#pragma unroll
                for (int b = 0; b < 4; b++)
                    *(float4*)&s->red[(w << 7) + (b << 5) + (l << 2)] =
                        make_float4(a[b][0], a[b][1], a[b][2], a[b][3]);
        }
        __syncthreads();

        // ---- final: h(t) ----
        if (tid < 128) {
            float sum = pm2;
#pragma unroll
            for (int k = 0; k < 16; k++) sum += s->red[(k << 7) + tid];
            float hh = tanhf(sum);
            float z  = s->zs[tid];
            float hp = s->hown[tid];
            out[((size_t)(gb0 + rb) * TT + t) * UU + j0 + rc] =
                z * hp + (1.0f - z) * hh;
        }
        ARRIVE(); ++tgt;
    }
}

// ===========================================================================
// Serial fallback (exact R10): mx_gemm then gru — used if SMs <= 128
// ===========================================================================
__global__ __launch_bounds__(256) void mx_gemm(const float* __restrict__ X,
                                               const float* __restrict__ W,
                                               const float* __restrict__ bias) {
    __shared__ float As[16][132];
    __shared__ float Bs[16][68];
    const int tid = threadIdx.x;
    const int m0  = blockIdx.y * 128;
    const int n0  = blockIdx.x * 64;
    const int tm  = tid & 15;
    const int tn  = tid >> 4;
    float acc[8][4];
#pragma unroll
    for (int i = 0; i < 8; i++)
#pragma unroll
        for (int j = 0; j < 4; j++) acc[i][j] = 0.0f;
    for (int kk = 0; kk < DD; kk += 16) {
#pragma unroll
        for (int jj = 0; jj < 2; jj++) {
            int idx = tid + jj * 256;
            int r   = idx >> 2;
            int kq  = (idx & 3) << 2;
            float4 v = *(const float4*)&X[(size_t)(m0 + r) * DD + kk + kq];
            As[kq + 0][r] = v.x; As[kq + 1][r] = v.y;
            As[kq + 2][r] = v.z; As[kq + 3][r] = v.w;
        }
        {
            int kr = tid >> 4;
            int nq = (tid & 15) << 2;
            float4 v = *(const float4*)&W[(size_t)(kk + kr) * (3 * UU) + n0 + nq];
            *(float4*)&Bs[kr][nq] = v;
        }
        __syncthreads();
#pragma unroll
        for (int k = 0; k < 16; k++) {
            float4 a0 = *(const float4*)&As[k][tm << 2];
            float4 a1 = *(const float4*)&As[k][64 + (tm << 2)];
            float4 b0 = *(const float4*)&Bs[k][tn << 2];
            float af[8] = {a0.x, a0.y, a0.z, a0.w, a1.x, a1.y, a1.z, a1.w};
            float bf[4] = {b0.x, b0.y, b0.z, b0.w};
#pragma unroll
            for (int i = 0; i < 8; i++)
#pragma unroll
                for (int j = 0; j < 4; j++) acc[i][j] = fmaf(af[i], bf[j], acc[i][j]);
        }
        __syncthreads();
    }
    float4 bv = *(const float4*)&bias[n0 + (tn << 2)];
#pragma unroll
    for (int i = 0; i < 8; i++) {
        int m = (i < 4) ? ((tm << 2) + i) : (64 + (tm << 2) + (i - 4));
        float4 o;
        o.x = acc[i][0] + bv.x; o.y = acc[i][1] + bv.y;
        o.z = acc[i][2] + bv.z; o.w = acc[i][3] + bv.w;
        *(float4*)&g_mx[(size_t)(m0 + m) * (3 * UU) + n0 + (tn << 2)] = o;
    }
}

__global__ void set_prog_full() {
    if (threadIdx.x < 4) g_prog[threadIdx.x] = 384u;
}

// ---------------------------------------------------------------------------
extern "C" void kernel_launch(void* const* d_in, const int* in_sizes, int n_in,
                              void* d_out, int out_size) {
    const float* x    = (const float*)d_in[0];
    const float* ker  = (const float*)d_in[1];
    const float* rk   = (const float*)d_in[2];
    const float* bias = (const float*)d_in[3];
    float* out = (float*)d_out;
    (void)in_sizes; (void)n_in; (void)out_size;

    static int sms = -1;
    if (sms < 0) {
        cudaFuncSetAttribute(gru_fused, cudaFuncAttributeMaxDynamicSharedMemorySize,
                             SMX_BYTES);
        int dev = 0;
        cudaGetDevice(&dev);
        cudaDeviceGetAttribute(&sms, cudaDevAttrMultiProcessorCount, dev);
        if (sms < 0) sms = 0;
    }

    if (sms > 128) {
        init_prog<<<1, 32>>>();
        gru_fused<<<sms, 512, SMX_BYTES>>>(x, ker, rk, bias, out);
    } else {
        // serial fallback: produce all mx first, mark chunks full, then scan
        dim3 gg(24, 128);
        mx_gemm<<<gg, 256>>>(x, ker, bias);
        set_prog_full<<<1, 32>>>();
        gru_fused<<<128, 512, SMX_BYTES>>>(x, ker, rk, bias, out);
    }
}

// round 14
// speedup vs baseline: 1.1931x; 1.1660x over previous
#include <cuda_runtime.h>
#include <cuda_bf16.h>
#include <cstdint>
#include <cstddef>

#define BB 32
#define TT 512
#define DD 512
#define UU 512

typedef unsigned long long ull;

// ---------------------------------------------------------------------------
// Device-global scratch (no cudaMalloc allowed)
// ---------------------------------------------------------------------------
__device__ float    g_mx[(size_t)BB * TT * 3 * UU];   // x@kernel + bias
__device__ float    g_rh[BB * UU];                    // r*h exchange buffer
__device__ unsigned g_cnt[8];                         // cumulative arrivals
__device__ unsigned g_ep[8];                          // published epoch

__device__ __forceinline__ float hsig(float x) {
    return fminf(fmaxf(fmaf(0.2f, x, 0.5f), 0.0f), 1.0f);
}

// packed f32x2 helpers (sm_100a)
#define FMA2(acc, a, b) \
    asm("fma.rn.f32x2 %0, %1, %2, %0;" : "+l"(acc) : "l"(a), "l"(b))
#define PACK2(out, x) \
    asm("mov.b64 %0, {%1, %1};" : "=l"(out) : "r"(__float_as_uint(x)))
#define UNPACK2(lo, hi, v) \
    asm("mov.b64 {%0, %1}, %2;" : "=r"(lo), "=r"(hi) : "l"(v))

// ---------------------------------------------------------------------------
// Kernel 1: mx = x @ kernel + bias   (M=16384, N=1536, K=512) — FFMA roofline
// ---------------------------------------------------------------------------
__global__ __launch_bounds__(256) void mx_gemm(const float* __restrict__ X,
                                               const float* __restrict__ W,
                                               const float* __restrict__ bias) {
    __shared__ float As[16][132];
    __shared__ float Bs[16][68];

    const int tid = threadIdx.x;
    const int m0  = blockIdx.y * 128;
    const int n0  = blockIdx.x * 64;
    const int tm  = tid & 15;
    const int tn  = tid >> 4;

    float acc[8][4];
#pragma unroll
    for (int i = 0; i < 8; i++)
#pragma unroll
        for (int j = 0; j < 4; j++) acc[i][j] = 0.0f;

    for (int kk = 0; kk < DD; kk += 16) {
#pragma unroll
        for (int jj = 0; jj < 2; jj++) {
            int idx = tid + jj * 256;
            int r   = idx >> 2;
            int kq  = (idx & 3) << 2;
            float4 v = *(const float4*)&X[(size_t)(m0 + r) * DD + kk + kq];
            As[kq + 0][r] = v.x;
            As[kq + 1][r] = v.y;
            As[kq + 2][r] = v.z;
            As[kq + 3][r] = v.w;
        }
        {
            int kr = tid >> 4;
            int nq = (tid & 15) << 2;
            float4 v = *(const float4*)&W[(size_t)(kk + kr) * (3 * UU) + n0 + nq];
            *(float4*)&Bs[kr][nq] = v;
        }
        __syncthreads();

#pragma unroll
        for (int k = 0; k < 16; k++) {
            float4 a0 = *(const float4*)&As[k][tm << 2];
            float4 a1 = *(const float4*)&As[k][64 + (tm << 2)];
            float4 b0 = *(const float4*)&Bs[k][tn << 2];
            float af[8] = {a0.x, a0.y, a0.z, a0.w, a1.x, a1.y, a1.z, a1.w};
            float bf[4] = {b0.x, b0.y, b0.z, b0.w};
#pragma unroll
            for (int i = 0; i < 8; i++)
#pragma unroll
                for (int j = 0; j < 4; j++) acc[i][j] = fmaf(af[i], bf[j], acc[i][j]);
        }
        __syncthreads();
    }

    float4 bv = *(const float4*)&bias[n0 + (tn << 2)];
#pragma unroll
    for (int i = 0; i < 8; i++) {
        int m = (i < 4) ? ((tm << 2) + i) : (64 + (tm << 2) + (i - 4));
        float4 o;
        o.x = acc[i][0] + bv.x;
        o.y = acc[i][1] + bv.y;
        o.z = acc[i][2] + bv.z;
        o.w = acc[i][3] + bv.w;
        *(float4*)&g_mx[(size_t)(m0 + m) * (3 * UU) + n0 + (tn << 2)] = o;
    }
}

#define RED2(v) do { \
    (v) += __shfl_xor_sync(0xffffffffu, (v), 8);  \
    (v) += __shfl_xor_sync(0xffffffffu, (v), 16); \
} while (0)

// ===========================================================================
// GRU recurrence (R10 structure + f32x2 math): 128 CTAs = 8 groups (x4
// batches) * 16 col-CTAs (x32 cols), 512 threads, 1 CTA/SM. R10's proven
// cumulative-atomic barrier (verbatim). z-GEMM hidden in rh window.
// ===========================================================================
struct SM16 {
    float wh[512 * 32];     // 64 KB
    float stage[4][512];    // 8 KB (h, then rh)
    float red[16 * 128];    // 8 KB
    float zs[128], hown[128];
    unsigned ep0;
};
#define SM16_BYTES ((int)sizeof(SM16))

__global__ __launch_bounds__(512, 1) void gru16(const float* __restrict__ RK,
                                                float* __restrict__ out) {
    extern __shared__ char raw[];
    SM16* s = (SM16*)raw;
    const int tid = threadIdx.x;
    const int grp = blockIdx.x >> 4;          // 0..7
    const int gb0 = grp << 2;
    const int j0  = (blockIdx.x & 15) << 5;   // 32 unit cols

    const int ks = tid >> 3;                  // 0..63, u = ks*8 .. +7
    const int cs = tid & 7;                   // cols cs*4 .. +3
    const int ub = ks << 3;
    const int w  = tid >> 5;
    const int l  = tid & 31;

    const int gate = tid >> 7;                // tid<256: 0=z, 1=r
    const int rb   = (tid >> 5) & 3;
    const int rc   = tid & 31;

    // ---- weights: Wh -> SMEM, Wz/Wr -> packed registers ----
    for (int i = tid; i < (512 * 32) / 4; i += 512) {
        int f = i << 2;
        int u = f >> 5, c = f & 31;
        *(float4*)&s->wh[f] = *(const float4*)&RK[(size_t)u * 1536 + 1024 + j0 + c];
    }
    ull wz01[8], wz23[8], wr01[8], wr23[8];
#pragma unroll
    for (int uu = 0; uu < 8; uu++) {
        const float* bp = &RK[(size_t)(ub + uu) * 1536 + j0 + (cs << 2)];
        float4 za = *(const float4*)bp;
        float4 ra = *(const float4*)(bp + 512);
        asm("mov.b64 %0, {%1, %2};" : "=l"(wz01[uu])
            : "r"(__float_as_uint(za.x)), "r"(__float_as_uint(za.y)));
        asm("mov.b64 %0, {%1, %2};" : "=l"(wz23[uu])
            : "r"(__float_as_uint(za.z)), "r"(__float_as_uint(za.w)));
        asm("mov.b64 %0, {%1, %2};" : "=l"(wr01[uu])
            : "r"(__float_as_uint(ra.x)), "r"(__float_as_uint(ra.y)));
        asm("mov.b64 %0, {%1, %2};" : "=l"(wr23[uu])
            : "r"(__float_as_uint(ra.z)), "r"(__float_as_uint(ra.w)));
    }

    if (tid == 0) s->ep0 = *(volatile unsigned*)&g_ep[grp];
    __syncthreads();
    const unsigned base = s->ep0;
    unsigned tgt = base;

    // R10's proven cumulative-counter barrier (verbatim).
    auto ARRIVE = [&]() {
        __threadfence();
        __syncthreads();
        if (tid == 0) {
            unsigned p = atomicAdd(&g_cnt[grp], 1u);
            if (((p + 1u) & 15u) == 0u) {
                __threadfence();
                *(volatile unsigned*)&g_ep[grp] = (p + 1u) >> 4;
            }
        }
    };
    auto WAIT = [&](unsigned target) {
        if (tid == 0) {
            while ((int)(*(volatile unsigned*)&g_ep[grp] - target) < 0) {
                __nanosleep(32);
            }
        }
        __syncthreads();
    };

    // ---- t = 0 : h_prev = 0 ----
    if (tid < 128) {
        size_t mrow = (size_t)(gb0 + rb) * TT * 1536;
        float z  = hsig(g_mx[mrow + j0 + rc]);
        float hh = tanhf(g_mx[mrow + 1024 + j0 + rc]);
        out[(size_t)(gb0 + rb) * TT * UU + j0 + rc] = (1.0f - z) * hh;
    }
    ARRIVE(); ++tgt;

#pragma unroll 1
    for (int t = 1; t < TT; t++) {
        // prefetch mx gate terms (independent of sync)
        float pm1 = 0.0f, pm2 = 0.0f;
        if (tid < 256) {
            size_t mrow = ((size_t)(gb0 + rb) * TT + t) * 1536;
            pm1 = __ldcg(&g_mx[mrow + (gate << 9) + j0 + rc]);
            if (tid < 128) pm2 = __ldcg(&g_mx[mrow + 1024 + j0 + rc]);
        }

        // ---- wait h(t-1) ----
        WAIT(tgt);

        // ---- stage h(t-1) ----
        {
            int b = tid >> 7, ug = tid & 127;
            float4 v = __ldcg(
                (const float4*)(out + ((size_t)(gb0 + b) * TT + (t - 1)) * UU) + ug);
            *(float4*)&s->stage[b][ug << 2] = v;
        }
        __syncthreads();

        // ---- r pass (packed f32x2, critical path) ----
        {
            ull p01[4] = {0, 0, 0, 0}, p23[4] = {0, 0, 0, 0};
#pragma unroll
            for (int uu = 0; uu < 8; uu++) {
                int u = ub + uu;
                ull w01 = wr01[uu], w23 = wr23[uu];
                ull h0p, h1p, h2p, h3p;
                PACK2(h0p, s->stage[0][u]);
                PACK2(h1p, s->stage[1][u]);
                PACK2(h2p, s->stage[2][u]);
                PACK2(h3p, s->stage[3][u]);
                FMA2(p01[0], h0p, w01); FMA2(p23[0], h0p, w23);
                FMA2(p01[1], h1p, w01); FMA2(p23[1], h1p, w23);
                FMA2(p01[2], h2p, w01); FMA2(p23[2], h2p, w23);
                FMA2(p01[3], h3p, w01); FMA2(p23[3], h3p, w23);
            }
            float a[4][4];
#pragma unroll
            for (int b = 0; b < 4; b++) {
                unsigned lo, hi;
                UNPACK2(lo, hi, p01[b]);
                a[b][0] = __uint_as_float(lo); a[b][1] = __uint_as_float(hi);
                UNPACK2(lo, hi, p23[b]);
                a[b][2] = __uint_as_float(lo); a[b][3] = __uint_as_float(hi);
            }
#pragma unroll
            for (int b = 0; b < 4; b++)
#pragma unroll
                for (int c = 0; c < 4; c++) RED2(a[b][c]);
            if (l < 8)
#pragma unroll
                for (int b = 0; b < 4; b++)
                    *(float4*)&s->red[(w << 7) + (b << 5) + (l << 2)] =
                        make_float4(a[b][0], a[b][1], a[b][2], a[b][3]);
        }
        __syncthreads();

        // ---- r reduce -> publish rh (threads 128..255 hold pm1 = mx_r) ----
        if (gate == 1 && tid < 256) {
            int idx = tid - 128;
            float sum = pm1;
#pragma unroll
            for (int k = 0; k < 16; k++) sum += s->red[(k << 7) + idx];
            float r = hsig(sum);
            g_rh[(size_t)(gb0 + rb) * UU + j0 + rc] = r * s->stage[rb][j0 + rc];
        }
        ARRIVE(); ++tgt;          // rh published  (no wait yet)

        // ======== hidden work: z pass while peers publish rh ========
        {
            ull p01[4] = {0, 0, 0, 0}, p23[4] = {0, 0, 0, 0};
#pragma unroll
            for (int uu = 0; uu < 8; uu++) {
                int u = ub + uu;
                ull w01 = wz01[uu], w23 = wz23[uu];
                ull h0p, h1p, h2p, h3p;
                PACK2(h0p, s->stage[0][u]);
                PACK2(h1p, s->stage[1][u]);
                PACK2(h2p, s->stage[2][u]);
                PACK2(h3p, s->stage[3][u]);
                FMA2(p01[0], h0p, w01); FMA2(p23[0], h0p, w23);
                FMA2(p01[1], h1p, w01); FMA2(p23[1], h1p, w23);
                FMA2(p01[2], h2p, w01); FMA2(p23[2], h2p, w23);
                FMA2(p01[3], h3p, w01); FMA2(p23[3], h3p, w23);
            }
            float a[4][4];
#pragma unroll
            for (int b = 0; b < 4; b++) {
                unsigned lo, hi;
                UNPACK2(lo, hi, p01[b]);
                a[b][0] = __uint_as_float(lo); a[b][1] = __uint_as_float(hi);
                UNPACK2(lo, hi, p23[b]);
                a[b][2] = __uint_as_float(lo); a[b][3] = __uint_as_float(hi);
            }
#pragma unroll
            for (int b = 0; b < 4; b++)
#pragma unroll
                for (int c = 0; c < 4; c++) RED2(a[b][c]);
            if (l < 8)
#pragma unroll
                for (int b = 0; b < 4; b++)
                    *(float4*)&s->red[(w << 7) + (b << 5) + (l << 2)] =
                        make_float4(a[b][0], a[b][1], a[b][2], a[b][3]);
        }
        __syncthreads();
        if (gate == 0 && tid < 128) {     // threads 0..127 hold pm1 = mx_z
            float sum = pm1;
#pragma unroll
            for (int k = 0; k < 16; k++) sum += s->red[(k << 7) + tid];
            s->zs[tid]   = hsig(sum);
            s->hown[tid] = s->stage[rb][j0 + rc];
        }
        // ============================================================

        // ---- wait rh from all group CTAs, stage it ----
        WAIT(tgt);
        {
            int b = tid >> 7, ug = tid & 127;
            float4 v = __ldcg((const float4*)(g_rh + (size_t)(gb0 + b) * UU) + ug);
            *(float4*)&s->stage[b][ug << 2] = v;
        }
        __syncthreads();

        // ---- h-candidate pass (Wh from SMEM, packed) ----
        {
            ull p01[4] = {0, 0, 0, 0}, p23[4] = {0, 0, 0, 0};
#pragma unroll
            for (int uu = 0; uu < 8; uu++) {
                int u = ub + uu;
                float4 wv = *(const float4*)&s->wh[(u << 5) + (cs << 2)];
                ull w01, w23;
                asm("mov.b64 %0, {%1, %2};" : "=l"(w01)
                    : "r"(__float_as_uint(wv.x)), "r"(__float_as_uint(wv.y)));
                asm("mov.b64 %0, {%1, %2};" : "=l"(w23)
                    : "r"(__float_as_uint(wv.z)), "r"(__float_as_uint(wv.w)));
                ull h0p, h1p, h2p, h3p;
                PACK2(h0p, s->stage[0][u]);
                PACK2(h1p, s->stage[1][u]);
                PACK2(h2p, s->stage[2][u]);
                PACK2(h3p, s->stage[3][u]);
                FMA2(p01[0], h0p, w01); FMA2(p23[0], h0p, w23);
                FMA2(p01[1], h1p, w01); FMA2(p23[1], h1p, w23);
                FMA2(p01[2], h2p, w01); FMA2(p23[2], h2p, w23);
                FMA2(p01[3], h3p, w01); FMA2(p23[3], h3p, w23);
            }
            float a[4][4];
#pragma unroll
            for (int b = 0; b < 4; b++) {
                unsigned lo, hi;
                UNPACK2(lo, hi, p01[b]);
                a[b][0] = __uint_as_float(lo); a[b][1] = __uint_as_float(hi);
                UNPACK2(lo, hi, p23[b]);
                a[b][2] = __uint_as_float(lo); a[b][3] = __uint_as_float(hi);
            }
#pragma unroll
            for (int b = 0; b < 4; b++)
#pragma unroll
                for (int c = 0; c < 4; c++) RED2(a[b][c]);
            if (l < 8)
#pragma unroll
                for (int b = 0; b < 4; b++)
                    *(float4*)&s->red[(w << 7) + (b << 5) + (l << 2)] =
                        make_float4(a[b][0], a[b][1], a[b][2], a[b][3]);
        }
        __syncthreads();

        // ---- final: h(t) ----
        if (tid < 128) {
            float sum = pm2;
#pragma unroll
            for (int k = 0; k < 16; k++) sum += s->red[(k << 7) + tid];
            float hh = tanhf(sum);
            float z  = s->zs[tid];
            float hp = s->hown[tid];
            out[((size_t)(gb0 + rb) * TT + t) * UU + j0 + rc] =
                z * hp + (1.0f - z) * hh;
        }
        ARRIVE(); ++tgt;          // h(t) published; wait at next loop top
    }
}

// ---------------------------------------------------------------------------
extern "C" void kernel_launch(void* const* d_in, const int* in_sizes, int n_in,
                              void* d_out, int out_size) {
    const float* x    = (const float*)d_in[0];
    const float* ker  = (const float*)d_in[1];
    const float* rk   = (const float*)d_in[2];
    const float* bias = (const float*)d_in[3];
    float* out = (float*)d_out;
    (void)in_sizes; (void)n_in; (void)out_size;

    static bool attr_set = false;
    if (!attr_set) {
        cudaFuncSetAttribute(gru16, cudaFuncAttributeMaxDynamicSharedMemorySize,
                             SM16_BYTES);
        attr_set = true;
    }

    dim3 gg(24, 128);
    mx_gemm<<<gg, 256>>>(x, ker, bias);
    gru16<<<128, 512, SM16_BYTES>>>(rk, out);
}